// round 7
// baseline (speedup 1.0000x reference)
#include <cuda_runtime.h>
#include <cuda_bf16.h>
#include <cstdint>

// TensorDLT closed-form solve for fixed source corners
// (0,0),(127,0),(127,127),(0,127). 8 fp32 in -> 9 fp32 out per element.
//
//   h2 = u1', h5 = v1'
//   a_i = (u_i'-u1')/127, c_i = (v1'-v_i')/127
//   2x2:  (u2'-u3') h6 + (u4'-u3') h7 = a3-a2-a4
//         (v3'-v2') h6 + (v3'-v4') h7 = c3-c2-c4
//   h0 = u2' h6 + a2, h1 = u4' h7 + a4, h3 = v2' h6 - c2, h4 = v4' h7 - c4
//
// R7: best-measured combo — warp-local SMEM staging (no block barrier),
// rcp.approx, BLOCK=128 for max occupancy, and a branch-free full-tile
// fast path (grid is exact for B % 128 == 0).

#define BLOCK 128

__device__ __forceinline__ float frcp_approx(float x) {
    float r;
    asm("rcp.approx.f32 %0, %1;" : "=f"(r) : "f"(x));
    return r;
}

struct H9 { float h[9]; };

__device__ __forceinline__ H9 dlt_solve(const float4 o0, const float4 o1) {
    const float up1 =   0.0f + 32.0f * o0.x;
    const float vp1 =   0.0f + 32.0f * o0.y;
    const float up2 = 127.0f + 32.0f * o0.z;
    const float vp2 =   0.0f + 32.0f * o0.w;
    const float up3 = 127.0f + 32.0f * o1.x;
    const float vp3 = 127.0f + 32.0f * o1.y;
    const float up4 =   0.0f + 32.0f * o1.z;
    const float vp4 = 127.0f + 32.0f * o1.w;

    const float inv127 = 1.0f / 127.0f;
    const float a2 = (up2 - up1) * inv127;
    const float a3 = (up3 - up1) * inv127;
    const float a4 = (up4 - up1) * inv127;
    const float c2 = (vp1 - vp2) * inv127;
    const float c3 = (vp1 - vp3) * inv127;
    const float c4 = (vp1 - vp4) * inv127;

    const float m00 = up2 - up3;
    const float m01 = up4 - up3;
    const float m10 = vp3 - vp2;
    const float m11 = vp3 - vp4;
    const float r0 = a3 - a2 - a4;
    const float r1 = c3 - c2 - c4;

    // det ~ +127^2 for |perturbation|<=32 -> well-conditioned; approx
    // reciprocal (rel err ~1e-7) is far inside the 1e-3 budget.
    const float invdet = frcp_approx(m00 * m11 - m01 * m10);
    const float h6 = (r0 * m11 - m01 * r1) * invdet;
    const float h7 = (m00 * r1 - r0 * m10) * invdet;

    H9 o;
    o.h[0] = up2 * h6 + a2;
    o.h[1] = up4 * h7 + a4;
    o.h[2] = up1;
    o.h[3] = vp2 * h6 - c2;
    o.h[4] = vp4 * h7 - c4;
    o.h[5] = vp1;
    o.h[6] = h6;
    o.h[7] = h7;
    o.h[8] = 1.0f;
    return o;
}

// Fast path: B % BLOCK == 0, no bounds checks anywhere.
__global__ void __launch_bounds__(BLOCK) tensor_dlt_full(
    const float* __restrict__ offset,  // [B, 8]
    float* __restrict__ out)           // [B, 9]
{
    __shared__ __align__(16) float s[BLOCK * 9];

    const int warp = threadIdx.x >> 5;
    const int lane = threadIdx.x & 31;
    const int b = blockIdx.x * BLOCK + threadIdx.x;

    const float4* p = reinterpret_cast<const float4*>(offset) + (size_t)b * 2;
    const float4 o0 = p[0];
    const float4 o1 = p[1];

    const H9 r = dlt_solve(o0, o1);

    // stride-9 STS: bank = (9*lane + c) mod 32, distinct per lane
    float* slice = s + warp * 288;
    float* row = slice + lane * 9;
    #pragma unroll
    for (int c = 0; c < 9; ++c) row[c] = r.h[c];

    __syncwarp();

    // Warp-coalesced flush: 72 float4 per 32-element warp slice.
    const int warpBase = blockIdx.x * BLOCK + warp * 32;
    const float4* s4 = reinterpret_cast<const float4*>(slice);
    float4* d4 = reinterpret_cast<float4*>(out + (size_t)warpBase * 9);
    d4[lane]      = s4[lane];
    d4[lane + 32] = s4[lane + 32];
    if (lane < 8)
        d4[lane + 64] = s4[lane + 64];
}

// Generic path with tail handling (only used when B % BLOCK != 0).
__global__ void __launch_bounds__(BLOCK) tensor_dlt_generic(
    const float* __restrict__ offset,
    float* __restrict__ out,
    int B)
{
    __shared__ __align__(16) float s[BLOCK * 9];

    const int warp = threadIdx.x >> 5;
    const int lane = threadIdx.x & 31;
    const int b = blockIdx.x * BLOCK + threadIdx.x;

    float* slice = s + warp * 288;

    if (b < B) {
        const float4* p = reinterpret_cast<const float4*>(offset) + (size_t)b * 2;
        const H9 r = dlt_solve(p[0], p[1]);
        float* row = slice + lane * 9;
        #pragma unroll
        for (int c = 0; c < 9; ++c) row[c] = r.h[c];
    }
    __syncwarp();

    const int warpBase = blockIdx.x * BLOCK + warp * 32;
    const int valid = min(32, B - warpBase);

    if (valid == 32) {
        const float4* s4 = reinterpret_cast<const float4*>(slice);
        float4* d4 = reinterpret_cast<float4*>(out + (size_t)warpBase * 9);
        d4[lane]      = s4[lane];
        d4[lane + 32] = s4[lane + 32];
        if (lane < 8)
            d4[lane + 64] = s4[lane + 64];
    } else if (valid > 0) {
        float* dst = out + (size_t)warpBase * 9;
        const int n = valid * 9;
        for (int i = lane; i < n; i += 32)
            dst[i] = slice[i];
    }
}

extern "C" void kernel_launch(void* const* d_in, const int* in_sizes, int n_in,
                              void* d_out, int out_size)
{
    const float* offset = (const float*)d_in[0];
    float* out = (float*)d_out;
    const int B = in_sizes[0] / 8;

    if (B % BLOCK == 0) {
        tensor_dlt_full<<<B / BLOCK, BLOCK>>>(offset, out);
    } else {
        tensor_dlt_generic<<<(B + BLOCK - 1) / BLOCK, BLOCK>>>(offset, out, B);
    }
}